// round 2
// baseline (speedup 1.0000x reference)
#include <cuda_runtime.h>
#include <math.h>

// ---------------------------------------------------------------------------
// Problem constants
// ---------------------------------------------------------------------------
#define N_TOK 49152          // B*M = 8192*6
#define NBLK  768            // N_TOK / 64
#define T2    120            // T*2
#define NEXP  5

// Output layout (float32, tuple concatenated flat)
#define OFF_FT  ((size_t)0)          // final_traj   [N,120]
#define OFF_FS  ((size_t)5898240)    // final_score  [N]
#define OFF_RL  ((size_t)5947392)    // router_logits[N,5]
#define OFF_TI  ((size_t)6193152)    // topk_idx     [N,2] (as float)
#define OFF_AX  ((size_t)6291456)    // aux_loss     [1]
#define OFF_TA  ((size_t)6291457)    // traj_all     [5,N,120]
#define OFF_SA  ((size_t)35782657)   // score_all    [5,N]

// ---------------------------------------------------------------------------
// Scratch (device globals -- no allocation allowed)
// ---------------------------------------------------------------------------
__device__ float g_shared_traj[(size_t)N_TOK * T2];
__device__ float g_shared_score[N_TOK];
__device__ float g_topk[(size_t)N_TOK * 4];    // i0, i1, p0, p1
__device__ float g_partial[NBLK * NEXP];       // per-block prob sums

__device__ __forceinline__ float gelu_f(float x) {
    return 0.5f * x * (1.0f + erff(x * 0.70710678118654752f));
}

// ---------------------------------------------------------------------------
// Generic dense layer: 64 tokens/block, 256 threads.
// thread = (tok = tid&63, sub = tid>>6); each sub owns a neuron quarter.
// Input/output rows live in smem with (odd) pitches PIN/POUT.
// ---------------------------------------------------------------------------
template<int DIN, int DOUT, bool GELU, int PIN, int POUT>
__device__ __forceinline__ void layer_fw(const float* __restrict__ W,
                                         const float* __restrict__ Bb,
                                         const float* Xs, float* Hs,
                                         int tok, int sub) {
    constexpr int quarter = (((DOUT + 3) / 4) + 7) & ~7;   // 8-aligned split
    const int jstart = sub * quarter;
    const int jend = (jstart + quarter < DOUT) ? (jstart + quarter) : DOUT;
    const float* xrow = Xs + tok * PIN;
    float* hrow = Hs + tok * POUT;

    int j = jstart;
    for (; j + 8 <= jend; j += 8) {
        float a0 = Bb[j+0], a1 = Bb[j+1], a2 = Bb[j+2], a3 = Bb[j+3];
        float a4 = Bb[j+4], a5 = Bb[j+5], a6 = Bb[j+6], a7 = Bb[j+7];
#pragma unroll 4
        for (int d = 0; d < DIN; ++d) {
            float xv = xrow[d];
            float4 w0 = *reinterpret_cast<const float4*>(W + (size_t)d * DOUT + j);
            float4 w1 = *reinterpret_cast<const float4*>(W + (size_t)d * DOUT + j + 4);
            a0 = fmaf(xv, w0.x, a0); a1 = fmaf(xv, w0.y, a1);
            a2 = fmaf(xv, w0.z, a2); a3 = fmaf(xv, w0.w, a3);
            a4 = fmaf(xv, w1.x, a4); a5 = fmaf(xv, w1.y, a5);
            a6 = fmaf(xv, w1.z, a6); a7 = fmaf(xv, w1.w, a7);
        }
        if (GELU) {
            a0 = gelu_f(a0); a1 = gelu_f(a1); a2 = gelu_f(a2); a3 = gelu_f(a3);
            a4 = gelu_f(a4); a5 = gelu_f(a5); a6 = gelu_f(a6); a7 = gelu_f(a7);
        }
        hrow[j+0] = a0; hrow[j+1] = a1; hrow[j+2] = a2; hrow[j+3] = a3;
        hrow[j+4] = a4; hrow[j+5] = a5; hrow[j+6] = a6; hrow[j+7] = a7;
    }
    for (; j < jend; ++j) {
        float a = Bb[j];
#pragma unroll 4
        for (int d = 0; d < DIN; ++d)
            a = fmaf(xrow[d], W[(size_t)d * DOUT + j], a);
        hrow[j] = GELU ? gelu_f(a) : a;
    }
}

__device__ __forceinline__ void stage_x(const float* __restrict__ x, float* Xs,
                                        int n0, int tid) {
    for (int k = tid; k < 64 * 32; k += 256) {       // 2048 float4 loads
        int tok = k >> 5, c4 = (k & 31) << 2;
        float4 v = *reinterpret_cast<const float4*>(x + (size_t)(n0 + tok) * 128 + c4);
        float* r = Xs + tok * 129 + c4;
        r[0] = v.x; r[1] = v.y; r[2] = v.z; r[3] = v.w;
    }
}

// ---------------------------------------------------------------------------
// Trajectory expert stack: 128 -> 256 -> 256 -> 120   (e==5 is the shared one)
// ---------------------------------------------------------------------------
#define TRAJ_SMEM ((64*129 + 2*64*257) * 4)
__global__ __launch_bounds__(256, 1)
void traj_kernel(const float* __restrict__ x,
                 const float* __restrict__ ew1, const float* __restrict__ eb1,
                 const float* __restrict__ ew2, const float* __restrict__ eb2,
                 const float* __restrict__ ew3, const float* __restrict__ eb3,
                 const float* __restrict__ sw1, const float* __restrict__ sb1,
                 const float* __restrict__ sw2, const float* __restrict__ sb2,
                 const float* __restrict__ sw3, const float* __restrict__ sb3,
                 float* __restrict__ out) {
    extern __shared__ float s[];
    float* Xs = s;                     // 64 x 129
    float* H1 = s + 64 * 129;          // 64 x 257
    float* H2 = H1 + 64 * 257;         // 64 x 257
    int tid = threadIdx.x, tok = tid & 63, sub = tid >> 6;
    int e = blockIdx.y, n0 = blockIdx.x * 64;

    const float *W1, *B1, *W2, *B2, *W3, *B3;
    if (e < NEXP) {
        W1 = ew1 + (size_t)e * 128 * 256; B1 = eb1 + e * 256;
        W2 = ew2 + (size_t)e * 256 * 256; B2 = eb2 + e * 256;
        W3 = ew3 + (size_t)e * 256 * T2;  B3 = eb3 + e * T2;
    } else {
        W1 = sw1; B1 = sb1; W2 = sw2; B2 = sb2; W3 = sw3; B3 = sb3;
    }

    stage_x(x, Xs, n0, tid);                       __syncthreads();
    layer_fw<128, 256, true, 129, 257>(W1, B1, Xs, H1, tok, sub); __syncthreads();
    layer_fw<256, 256, true, 257, 257>(W2, B2, H1, H2, tok, sub); __syncthreads();
    layer_fw<256, T2, false, 257, 129>(W3, B3, H2, Xs, tok, sub); __syncthreads();

    float* dst = (e < NEXP) ? (out + OFF_TA + (size_t)e * N_TOK * T2)
                            : g_shared_traj;
    for (int k = tid; k < 64 * T2; k += 256)
        dst[(size_t)n0 * T2 + k] = Xs[(k / T2) * 129 + (k % T2)];
}

// ---------------------------------------------------------------------------
// Score expert stack: 128 -> 128 -> 64 -> 1
// ---------------------------------------------------------------------------
#define SCORE_SMEM ((64*129 + 64*129 + 64*65) * 4)
__global__ __launch_bounds__(256, 1)
void score_kernel(const float* __restrict__ x,
                  const float* __restrict__ ew1, const float* __restrict__ eb1,
                  const float* __restrict__ ew2, const float* __restrict__ eb2,
                  const float* __restrict__ ew3, const float* __restrict__ eb3,
                  const float* __restrict__ sw1, const float* __restrict__ sb1,
                  const float* __restrict__ sw2, const float* __restrict__ sb2,
                  const float* __restrict__ sw3, const float* __restrict__ sb3,
                  float* __restrict__ out) {
    extern __shared__ float s[];
    float* Xs = s;                     // 64 x 129
    float* H1 = s + 64 * 129;          // 64 x 129
    float* H2 = H1 + 64 * 129;         // 64 x 65
    int tid = threadIdx.x, tok = tid & 63, sub = tid >> 6;
    int e = blockIdx.y, n0 = blockIdx.x * 64;

    const float *W1, *B1, *W2, *B2, *W3, *B3;
    if (e < NEXP) {
        W1 = ew1 + (size_t)e * 128 * 128; B1 = eb1 + e * 128;
        W2 = ew2 + (size_t)e * 128 * 64;  B2 = eb2 + e * 64;
        W3 = ew3 + (size_t)e * 64;        B3 = eb3 + e;
    } else {
        W1 = sw1; B1 = sb1; W2 = sw2; B2 = sb2; W3 = sw3; B3 = sb3;
    }

    stage_x(x, Xs, n0, tid);                        __syncthreads();
    layer_fw<128, 128, true, 129, 129>(W1, B1, Xs, H1, tok, sub); __syncthreads();
    layer_fw<128, 64, true, 129, 65>(W2, B2, H1, H2, tok, sub);   __syncthreads();

    if (tid < 64) {
        float a = B3[0];
#pragma unroll
        for (int d = 0; d < 64; ++d)
            a = fmaf(H2[tid * 65 + d], W3[d], a);
        float* dst = (e < NEXP) ? (out + OFF_SA + (size_t)e * N_TOK)
                                : g_shared_score;
        dst[n0 + tid] = a;
    }
}

// ---------------------------------------------------------------------------
// Router: 128 -> 256 -> 128 -> 5, softmax, top-2, per-block prob partials
// ---------------------------------------------------------------------------
#define ROUTER_SMEM ((64*129 + 64*257 + 64*129) * 4)
__global__ __launch_bounds__(256, 1)
void router_kernel(const float* __restrict__ x,
                   const float* __restrict__ w1, const float* __restrict__ b1,
                   const float* __restrict__ w2, const float* __restrict__ b2,
                   const float* __restrict__ w3, const float* __restrict__ b3,
                   float* __restrict__ out) {
    extern __shared__ float s[];
    float* Xs = s;                     // 64 x 129 (also holds logits after L3)
    float* H1 = s + 64 * 129;          // 64 x 257 (reused as probs P[64][8])
    float* H2 = H1 + 64 * 257;         // 64 x 129
    int tid = threadIdx.x, tok = tid & 63, sub = tid >> 6;
    int n0 = blockIdx.x * 64;

    stage_x(x, Xs, n0, tid);                        __syncthreads();
    layer_fw<128, 256, true, 129, 257>(w1, b1, Xs, H1, tok, sub); __syncthreads();
    layer_fw<256, 128, true, 257, 129>(w2, b2, H1, H2, tok, sub); __syncthreads();
    layer_fw<128, 5, false, 129, 129>(w3, b3, H2, Xs, tok, sub);  __syncthreads();

    if (tid < 64) {
        int n = n0 + tid;
        float l[5];
#pragma unroll
        for (int e = 0; e < 5; ++e) {
            l[e] = Xs[tid * 129 + e];
            out[OFF_RL + (size_t)n * 5 + e] = l[e];
        }
        // top-2 (ties -> lower index, matching lax.top_k)
        int i0 = 0;
#pragma unroll
        for (int e = 1; e < 5; ++e) if (l[e] > l[i0]) i0 = e;
        int i1 = (i0 == 0) ? 1 : 0;
#pragma unroll
        for (int e = 0; e < 5; ++e) if (e != i0 && l[e] > l[i1]) i1 = e;
        float p0 = 1.0f / (1.0f + expf(l[i1] - l[i0]));
        float p1 = 1.0f - p0;
        out[OFF_TI + (size_t)n * 2 + 0] = (float)i0;
        out[OFF_TI + (size_t)n * 2 + 1] = (float)i1;
        float4 q; q.x = (float)i0; q.y = (float)i1; q.z = p0; q.w = p1;
        *reinterpret_cast<float4*>(g_topk + (size_t)n * 4) = q;
        // full softmax over 5 for the aux loss
        float m = l[0];
#pragma unroll
        for (int e = 1; e < 5; ++e) m = fmaxf(m, l[e]);
        float ssum = 0.f, pe[5];
#pragma unroll
        for (int e = 0; e < 5; ++e) { pe[e] = expf(l[e] - m); ssum += pe[e]; }
        float inv = 1.0f / ssum;
#pragma unroll
        for (int e = 0; e < 5; ++e) H1[tid * 8 + e] = pe[e] * inv;
    }
    __syncthreads();
    // deterministic tree reduce over 64 tokens
    for (int st = 32; st > 0; st >>= 1) {
        if (tid < st) {
#pragma unroll
            for (int e = 0; e < 5; ++e)
                H1[tid * 8 + e] += H1[(tid + st) * 8 + e];
        }
        __syncthreads();
    }
    if (tid == 0) {
#pragma unroll
        for (int e = 0; e < 5; ++e)
            g_partial[blockIdx.x * 5 + e] = H1[e];
    }
}

// ---------------------------------------------------------------------------
// Aux loss finalize (fixed order -> deterministic)
// ---------------------------------------------------------------------------
__global__ void aux_kernel(float* __restrict__ out) {
    __shared__ float sums[5];
    int e = threadIdx.x;
    if (e < 5) {
        float acc = 0.f;
        for (int b = 0; b < NBLK; ++b) acc += g_partial[b * 5 + e];
        sums[e] = acc;
    }
    __syncthreads();
    if (threadIdx.x == 0) {
        float ent = 0.f, l2 = 0.f;
#pragma unroll
        for (int k = 0; k < 5; ++k) {
            float avg = sums[k] * (1.0f / (float)N_TOK);
            ent -= avg * logf(avg + 1e-8f);
            float d = avg - 0.2f;
            l2 += d * d;
        }
        l2 *= 0.2f;
        out[OFF_AX] = -ent * 0.01f + 0.01f * l2;
    }
}

// ---------------------------------------------------------------------------
// Top-k combine
// ---------------------------------------------------------------------------
__global__ __launch_bounds__(256)
void combine_traj_kernel(const float* __restrict__ src, float* __restrict__ out) {
    int g = blockIdx.x * 256 + threadIdx.x;           // grid sized exactly
    int n = g / T2, c = g - n * T2;
    float4 q = *reinterpret_cast<const float4*>(g_topk + (size_t)n * 4);
    int i0 = (int)q.x, i1 = (int)q.y;
    float t0 = src[OFF_TA + ((size_t)i0 * N_TOK + n) * T2 + c];
    float t1 = src[OFF_TA + ((size_t)i1 * N_TOK + n) * T2 + c];
    out[OFF_FT + g] = 0.3f * g_shared_traj[g] + 0.7f * (q.z * t0 + q.w * t1);
}

__global__ __launch_bounds__(256)
void combine_score_kernel(const float* __restrict__ src, float* __restrict__ out) {
    int n = blockIdx.x * 256 + threadIdx.x;
    float4 q = *reinterpret_cast<const float4*>(g_topk + (size_t)n * 4);
    int i0 = (int)q.x, i1 = (int)q.y;
    float s0 = src[OFF_SA + (size_t)i0 * N_TOK + n];
    float s1 = src[OFF_SA + (size_t)i1 * N_TOK + n];
    out[OFF_FS + n] = 0.3f * g_shared_score[n] + 0.7f * (q.z * s0 + q.w * s1);
}

// ---------------------------------------------------------------------------
// Launch
// ---------------------------------------------------------------------------
extern "C" void kernel_launch(void* const* d_in, const int* in_sizes, int n_in,
                              void* d_out, int out_size) {
    const float* x    = (const float*)d_in[0];
    const float* rw1  = (const float*)d_in[1];  const float* rb1 = (const float*)d_in[2];
    const float* rw2  = (const float*)d_in[3];  const float* rb2 = (const float*)d_in[4];
    const float* rw3  = (const float*)d_in[5];  const float* rb3 = (const float*)d_in[6];
    const float* stw1 = (const float*)d_in[7];  const float* stb1 = (const float*)d_in[8];
    const float* stw2 = (const float*)d_in[9];  const float* stb2 = (const float*)d_in[10];
    const float* stw3 = (const float*)d_in[11]; const float* stb3 = (const float*)d_in[12];
    const float* ssw1 = (const float*)d_in[13]; const float* ssb1 = (const float*)d_in[14];
    const float* ssw2 = (const float*)d_in[15]; const float* ssb2 = (const float*)d_in[16];
    const float* ssw3 = (const float*)d_in[17]; const float* ssb3 = (const float*)d_in[18];
    const float* etw1 = (const float*)d_in[19]; const float* etb1 = (const float*)d_in[20];
    const float* etw2 = (const float*)d_in[21]; const float* etb2 = (const float*)d_in[22];
    const float* etw3 = (const float*)d_in[23]; const float* etb3 = (const float*)d_in[24];
    const float* esw1 = (const float*)d_in[25]; const float* esb1 = (const float*)d_in[26];
    const float* esw2 = (const float*)d_in[27]; const float* esb2 = (const float*)d_in[28];
    const float* esw3 = (const float*)d_in[29]; const float* esb3 = (const float*)d_in[30];
    float* out = (float*)d_out;

    cudaFuncSetAttribute(traj_kernel,   cudaFuncAttributeMaxDynamicSharedMemorySize, TRAJ_SMEM);
    cudaFuncSetAttribute(score_kernel,  cudaFuncAttributeMaxDynamicSharedMemorySize, SCORE_SMEM);
    cudaFuncSetAttribute(router_kernel, cudaFuncAttributeMaxDynamicSharedMemorySize, ROUTER_SMEM);

    router_kernel<<<NBLK, 256, ROUTER_SMEM>>>(x, rw1, rb1, rw2, rb2, rw3, rb3, out);

    dim3 gT(NBLK, 6);
    traj_kernel<<<gT, 256, TRAJ_SMEM>>>(x, etw1, etb1, etw2, etb2, etw3, etb3,
                                        stw1, stb1, stw2, stb2, stw3, stb3, out);
    score_kernel<<<gT, 256, SCORE_SMEM>>>(x, esw1, esb1, esw2, esb2, esw3, esb3,
                                          ssw1, ssb1, ssw2, ssb2, ssw3, ssb3, out);

    aux_kernel<<<1, 32>>>(out);

    combine_traj_kernel<<<(N_TOK * T2) / 256, 256>>>(out, out);
    combine_score_kernel<<<N_TOK / 256, 256>>>(out, out);
}

// round 17
// speedup vs baseline: 3.7361x; 3.7361x over previous
#include <cuda_runtime.h>
#include <cuda_fp16.h>
#include <math.h>
#include <stdint.h>

// ---------------------------------------------------------------------------
// Problem constants
// ---------------------------------------------------------------------------
#define N_TOK 49152          // B*M
#define NBLK  768            // N_TOK / 64   (router/score blocking)
#define T2    120
#define NEXP  5

// Output layout (float32, tuple concatenated flat)
#define OFF_FT  ((size_t)0)
#define OFF_FS  ((size_t)5898240)
#define OFF_RL  ((size_t)5947392)
#define OFF_TI  ((size_t)6193152)
#define OFF_AX  ((size_t)6291456)
#define OFF_TA  ((size_t)6291457)
#define OFF_SA  ((size_t)35782657)

// ---------------------------------------------------------------------------
// Device scratch
// ---------------------------------------------------------------------------
__device__ float g_shared_traj[(size_t)N_TOK * T2];
__device__ float g_shared_score[N_TOK];
__device__ float g_topk[(size_t)N_TOK * 4];
__device__ float g_partial[NBLK * NEXP];
// fp16 weight images, W^T row-major [n][k] with padded pitch (K/2+4 u32 words):
// W1: 6 experts x 256 rows x 68 w ; W2: 6 x 256 x 132 ; W3: 6 x 120 x 132
#define GW_W1 0
#define GW_W2 104448
#define GW_W3 307200
__device__ __align__(16) uint32_t g_wt[402240];

__device__ __forceinline__ float gelu_f(float x) {
    return 0.5f * x * (1.0f + erff(x * 0.70710678118654752f));
}
__device__ __forceinline__ uint32_t pack_h2(float a, float b) {
    __half2 h = __floats2half2_rn(a, b);
    return *reinterpret_cast<uint32_t*>(&h);
}

// ---------------------------------------------------------------------------
// Prep: fp32 weights -> fp16 W^T images (row n, k contiguous, padded pitch)
// ---------------------------------------------------------------------------
__global__ __launch_bounds__(256)
void prep_kernel(const float* __restrict__ etw1, const float* __restrict__ etw2,
                 const float* __restrict__ etw3,
                 const float* __restrict__ stw1, const float* __restrict__ stw2,
                 const float* __restrict__ stw3) {
    int i = blockIdx.x * 256 + threadIdx.x;
    if (i >= 402240) return;
    if (i < 104448) {                         // W1 [128k][256n] -> [256n][68w]
        int e = i / 17408, r = i % 17408;
        int n = r / 68, kw = r % 68, kp = kw * 2;
        const float* W = (e < NEXP) ? etw1 + (size_t)e * 128 * 256 : stw1;
        uint32_t v = 0;
        if (kp < 128) v = pack_h2(W[kp * 256 + n], W[(kp + 1) * 256 + n]);
        g_wt[GW_W1 + e * 17408 + n * 68 + kw] = v;
    } else if (i < 307200) {                  // W2 [256k][256n] -> [256n][132w]
        int i2 = i - 104448;
        int e = i2 / 33792, r = i2 % 33792;
        int n = r / 132, kw = r % 132, kp = kw * 2;
        const float* W = (e < NEXP) ? etw2 + (size_t)e * 256 * 256 : stw2;
        uint32_t v = 0;
        if (kp < 256) v = pack_h2(W[kp * 256 + n], W[(kp + 1) * 256 + n]);
        g_wt[GW_W2 + e * 33792 + n * 132 + kw] = v;
    } else {                                  // W3 [256k][120n] -> [120n][132w]
        int i3 = i - 307200;
        int e = i3 / 15840, r = i3 % 15840;
        int n = r / 132, kw = r % 132, kp = kw * 2;
        const float* W = (e < NEXP) ? etw3 + (size_t)e * 256 * T2 : stw3;
        uint32_t v = 0;
        if (kp < 256) v = pack_h2(W[kp * T2 + n], W[(kp + 1) * T2 + n]);
        g_wt[GW_W3 + e * 15840 + n * 132 + kw] = v;
    }
}

// ---------------------------------------------------------------------------
// mma.sync m16n8k16 layer: warp computes 16 rows x NT*8 cols, K = KT*16.
// As: [rows][PA words] fp16 pairs (k contiguous); Ws: [n][PB words].
// Fragment loads hit banks 4g+q (+4nt) -> conflict-free.
// ---------------------------------------------------------------------------
template<int KT, int NT, int PA, int PB>
__device__ __forceinline__ void mma_layer(const uint32_t* As, const uint32_t* Ws,
                                          float* acc, int m0, int g, int q) {
    const uint32_t* ar0 = As + (m0 + g) * PA + q;
    const uint32_t* ar1 = As + (m0 + g + 8) * PA + q;
#pragma unroll 1
    for (int kt = 0; kt < KT; ++kt) {
        uint32_t a0 = ar0[kt * 8];
        uint32_t a1 = ar1[kt * 8];
        uint32_t a2 = ar0[kt * 8 + 4];
        uint32_t a3 = ar1[kt * 8 + 4];
        const uint32_t* bp = Ws + g * PB + kt * 8 + q;
#pragma unroll
        for (int nt = 0; nt < NT; ++nt) {
            uint32_t b0 = bp[nt * 8 * PB];
            uint32_t b1 = bp[nt * 8 * PB + 4];
            float* c = acc + nt * 4;
            asm volatile(
                "mma.sync.aligned.m16n8k16.row.col.f32.f16.f16.f32 "
                "{%0,%1,%2,%3}, {%4,%5,%6,%7}, {%8,%9}, {%0,%1,%2,%3};"
                : "+f"(c[0]), "+f"(c[1]), "+f"(c[2]), "+f"(c[3])
                : "r"(a0), "r"(a1), "r"(a2), "r"(a3), "r"(b0), "r"(b1));
        }
    }
}

// bias + gelu + fp16 pack -> smem activation tile (pitch 132 words)
template<int NT>
__device__ __forceinline__ void epi_gelu(const float* acc, uint32_t* Dst,
                                         const float* Bs, int m0, int g, int q) {
#pragma unroll
    for (int nt = 0; nt < NT; ++nt) {
        int j = nt * 8 + q * 2;
        float b0 = Bs[j], b1 = Bs[j + 1];
        const float* c = acc + nt * 4;
        Dst[(m0 + g) * 132 + nt * 4 + q]     = pack_h2(gelu_f(c[0] + b0), gelu_f(c[1] + b1));
        Dst[(m0 + g + 8) * 132 + nt * 4 + q] = pack_h2(gelu_f(c[2] + b0), gelu_f(c[3] + b1));
    }
}

// ---------------------------------------------------------------------------
// Traj expert stack (mma.sync): 128 tokens/block, grid (384, 6)
// smem (u32 words): phase1: A1@0(8704) W1@8704(17408)
//                   phase2: A2@0(16896) W2@16896(33792)
//                   phase3: A3@0(16896) W3@16896(15840)
//                   biases @50688 (B1 256f, B2 256f, B3 120f)
// ---------------------------------------------------------------------------
#define SW_W1  8704
#define SW_W23 16896
#define SW_B1  50688
#define SW_B2  50944
#define SW_B3  51200
#define SMEM_TC_B (51328 * 4)

__global__ __launch_bounds__(256, 1)
void traj_mma_kernel(const float* __restrict__ x,
                     const float* __restrict__ eb1, const float* __restrict__ eb2,
                     const float* __restrict__ eb3,
                     const float* __restrict__ sb1, const float* __restrict__ sb2,
                     const float* __restrict__ sb3,
                     float* __restrict__ out) {
    extern __shared__ uint32_t sm[];
    int tid = threadIdx.x, w = tid >> 5, t = tid & 31, g = t >> 2, q = t & 3;
    int e = blockIdx.y, n0 = blockIdx.x * 128, m0 = w * 16;

    float* B1s = (float*)(sm + SW_B1);
    float* B2s = (float*)(sm + SW_B2);
    float* B3s = (float*)(sm + SW_B3);
    {
        const float* B1 = (e < NEXP) ? eb1 + e * 256 : sb1;
        const float* B2 = (e < NEXP) ? eb2 + e * 256 : sb2;
        const float* B3 = (e < NEXP) ? eb3 + e * T2  : sb3;
        B1s[tid] = B1[tid];
        B2s[tid] = B2[tid];
        if (tid < T2) B3s[tid] = B3[tid];
    }
    // A1 stage: 128 tokens x 128 feats fp32 -> fp16 pairs, pitch 68 words
    for (int idx = tid; idx < 4096; idx += 256) {
        int n = idx >> 5, kq = idx & 31;
        float4 v = *reinterpret_cast<const float4*>(x + (size_t)(n0 + n) * 128 + kq * 4);
        uint2 u; u.x = pack_h2(v.x, v.y); u.y = pack_h2(v.z, v.w);
        *reinterpret_cast<uint2*>(sm + n * 68 + kq * 2) = u;
    }
    // W1 copy
    {
        const uint4* s1 = (const uint4*)(g_wt + GW_W1) + (size_t)e * 4352;
        uint4* d1 = (uint4*)(sm + SW_W1);
        for (int i = tid; i < 4352; i += 256) d1[i] = s1[i];
    }
    __syncthreads();

    // ---- layer 1: [128,128] x W1^T -> [128,256] ----
    float acc[128];
#pragma unroll
    for (int i = 0; i < 128; ++i) acc[i] = 0.f;
    mma_layer<8, 32, 68, 68>(sm, sm + SW_W1, acc, m0, g, q);
    __syncthreads();
    epi_gelu<32>(acc, sm, B1s, m0, g, q);     // A2 @ 0, pitch 132
    {
        const uint4* s2 = (const uint4*)(g_wt + GW_W2) + (size_t)e * 8448;
        uint4* d2 = (uint4*)(sm + SW_W23);
        for (int i = tid; i < 8448; i += 256) d2[i] = s2[i];
    }
    __syncthreads();

    // ---- layer 2: [128,256] x W2^T -> [128,256] ----
#pragma unroll
    for (int i = 0; i < 128; ++i) acc[i] = 0.f;
    mma_layer<16, 32, 132, 132>(sm, sm + SW_W23, acc, m0, g, q);
    __syncthreads();
    epi_gelu<32>(acc, sm, B2s, m0, g, q);     // A3 @ 0, pitch 132
    {
        const uint4* s3 = (const uint4*)(g_wt + GW_W3) + (size_t)e * 3960;
        uint4* d3 = (uint4*)(sm + SW_W23);
        for (int i = tid; i < 3960; i += 256) d3[i] = s3[i];
    }
    __syncthreads();

    // ---- layer 3: [128,256] x W3^T -> [128,120], bias only, direct gmem ----
    // NOTE: out+OFF_TA is only 4-byte aligned (OFF_TA odd) -> scalar stores only.
    float acc3[60];
#pragma unroll
    for (int i = 0; i < 60; ++i) acc3[i] = 0.f;
    mma_layer<16, 15, 132, 132>(sm, sm + SW_W23, acc3, m0, g, q);

    float* dst = (e < NEXP) ? (out + OFF_TA + (size_t)e * N_TOK * T2) : g_shared_traj;
    size_t r0 = (size_t)(n0 + m0 + g), r1 = r0 + 8;
#pragma unroll
    for (int nt = 0; nt < 15; ++nt) {
        int j = nt * 8 + q * 2;
        float b0 = B3s[j], b1 = B3s[j + 1];
        const float* c = acc3 + nt * 4;
        dst[r0 * T2 + j]     = c[0] + b0;
        dst[r0 * T2 + j + 1] = c[1] + b1;
        dst[r1 * T2 + j]     = c[2] + b0;
        dst[r1 * T2 + j + 1] = c[3] + b1;
    }
}

// ---------------------------------------------------------------------------
// fp32 layer helper (router / score)
// ---------------------------------------------------------------------------
template<int DIN, int DOUT, bool GELU, int PIN, int POUT>
__device__ __forceinline__ void layer_fw(const float* __restrict__ W,
                                         const float* __restrict__ Bb,
                                         const float* Xs, float* Hs,
                                         int tok, int sub) {
    constexpr int quarter = (((DOUT + 3) / 4) + 7) & ~7;
    const int jstart = sub * quarter;
    const int jend = (jstart + quarter < DOUT) ? (jstart + quarter) : DOUT;
    const float* xrow = Xs + tok * PIN;
    float* hrow = Hs + tok * POUT;

    int j = jstart;
    for (; j + 8 <= jend; j += 8) {
        float a0 = Bb[j+0], a1 = Bb[j+1], a2 = Bb[j+2], a3 = Bb[j+3];
        float a4 = Bb[j+4], a5 = Bb[j+5], a6 = Bb[j+6], a7 = Bb[j+7];
#pragma unroll 4
        for (int d = 0; d < DIN; ++d) {
            float xv = xrow[d];
            float4 w0 = *reinterpret_cast<const float4*>(W + (size_t)d * DOUT + j);
            float4 w1 = *reinterpret_cast<const float4*>(W + (size_t)d * DOUT + j + 4);
            a0 = fmaf(xv, w0.x, a0); a1 = fmaf(xv, w0.y, a1);
            a2 = fmaf(xv, w0.z, a2); a3 = fmaf(xv, w0.w, a3);
            a4 = fmaf(xv, w1.x, a4); a5 = fmaf(xv, w1.y, a5);
            a6 = fmaf(xv, w1.z, a6); a7 = fmaf(xv, w1.w, a7);
        }
        if (GELU) {
            a0 = gelu_f(a0); a1 = gelu_f(a1); a2 = gelu_f(a2); a3 = gelu_f(a3);
            a4 = gelu_f(a4); a5 = gelu_f(a5); a6 = gelu_f(a6); a7 = gelu_f(a7);
        }
        hrow[j+0] = a0; hrow[j+1] = a1; hrow[j+2] = a2; hrow[j+3] = a3;
        hrow[j+4] = a4; hrow[j+5] = a5; hrow[j+6] = a6; hrow[j+7] = a7;
    }
    for (; j < jend; ++j) {
        float a = Bb[j];
#pragma unroll 4
        for (int d = 0; d < DIN; ++d)
            a = fmaf(xrow[d], W[(size_t)d * DOUT + j], a);
        hrow[j] = GELU ? gelu_f(a) : a;
    }
}

__device__ __forceinline__ void stage_x(const float* __restrict__ x, float* Xs,
                                        int n0, int tid) {
    for (int k = tid; k < 64 * 32; k += 256) {
        int tok = k >> 5, c4 = (k & 31) << 2;
        float4 v = *reinterpret_cast<const float4*>(x + (size_t)(n0 + tok) * 128 + c4);
        float* r = Xs + tok * 129 + c4;
        r[0] = v.x; r[1] = v.y; r[2] = v.z; r[3] = v.w;
    }
}

// ---------------------------------------------------------------------------
// Score expert stack: 128 -> 128 -> 64 -> 1   (2 CTAs/SM)
// ---------------------------------------------------------------------------
#define SCORE_SMEM ((64*129 + 64*129 + 64*65) * 4)
__global__ __launch_bounds__(256, 2)
void score_kernel(const float* __restrict__ x,
                  const float* __restrict__ ew1, const float* __restrict__ eb1,
                  const float* __restrict__ ew2, const float* __restrict__ eb2,
                  const float* __restrict__ ew3, const float* __restrict__ eb3,
                  const float* __restrict__ sw1, const float* __restrict__ sb1,
                  const float* __restrict__ sw2, const float* __restrict__ sb2,
                  const float* __restrict__ sw3, const float* __restrict__ sb3,
                  float* __restrict__ out) {
    extern __shared__ float s[];
    float* Xs = s;
    float* H1 = s + 64 * 129;
    float* H2 = H1 + 64 * 129;
    int tid = threadIdx.x, tok = tid & 63, sub = tid >> 6;
    int e = blockIdx.y, n0 = blockIdx.x * 64;

    const float *W1, *B1, *W2, *B2, *W3, *B3;
    if (e < NEXP) {
        W1 = ew1 + (size_t)e * 128 * 128; B1 = eb1 + e * 128;
        W2 = ew2 + (size_t)e * 128 * 64;  B2 = eb2 + e * 64;
        W3 = ew3 + (size_t)e * 64;        B3 = eb3 + e;
    } else {
        W1 = sw1; B1 = sb1; W2 = sw2; B2 = sb2; W3 = sw3; B3 = sb3;
    }

    stage_x(x, Xs, n0, tid);                        __syncthreads();
    layer_fw<128, 128, true, 129, 129>(W1, B1, Xs, H1, tok, sub); __syncthreads();
    layer_fw<128, 64, true, 129, 65>(W2, B2, H1, H2, tok, sub);   __syncthreads();

    if (tid < 64) {
        float a = B3[0];
#pragma unroll
        for (int d = 0; d < 64; ++d)
            a = fmaf(H2[tid * 65 + d], W3[d], a);
        float* dst = (e < NEXP) ? (out + OFF_SA + (size_t)e * N_TOK) : g_shared_score;
        dst[n0 + tid] = a;
    }
}

// ---------------------------------------------------------------------------
// Router: 128 -> 256 -> 128 -> 5
// ---------------------------------------------------------------------------
#define ROUTER_SMEM ((64*129 + 64*257 + 64*129) * 4)
__global__ __launch_bounds__(256, 1)
void router_kernel(const float* __restrict__ x,
                   const float* __restrict__ w1, const float* __restrict__ b1,
                   const float* __restrict__ w2, const float* __restrict__ b2,
                   const float* __restrict__ w3, const float* __restrict__ b3,
                   float* __restrict__ out) {
    extern __shared__ float s[];
    float* Xs = s;
    float* H1 = s + 64 * 129;
    float* H2 = H1 + 64 * 257;
    int tid = threadIdx.x, tok = tid & 63, sub = tid >> 6;
    int n0 = blockIdx.x * 64;

    stage_x(x, Xs, n0, tid);                        __syncthreads();
    layer_fw<128, 256, true, 129, 257>(w1, b1, Xs, H1, tok, sub); __syncthreads();
    layer_fw<256, 128, true, 257, 129>(w2, b2, H1, H2, tok, sub); __syncthreads();
    layer_fw<128, 5, false, 129, 129>(w3, b3, H2, Xs, tok, sub);  __syncthreads();

    if (tid < 64) {
        int n = n0 + tid;
        float l[5];
#pragma unroll
        for (int e = 0; e < 5; ++e) {
            l[e] = Xs[tid * 129 + e];
            out[OFF_RL + (size_t)n * 5 + e] = l[e];
        }
        int i0 = 0;
#pragma unroll
        for (int e = 1; e < 5; ++e) if (l[e] > l[i0]) i0 = e;
        int i1 = (i0 == 0) ? 1 : 0;
#pragma unroll
        for (int e = 0; e < 5; ++e) if (e != i0 && l[e] > l[i1]) i1 = e;
        float p0 = 1.0f / (1.0f + expf(l[i1] - l[i0]));
        float p1 = 1.0f - p0;
        out[OFF_TI + (size_t)n * 2 + 0] = (float)i0;
        out[OFF_TI + (size_t)n * 2 + 1] = (float)i1;
        float4 qv; qv.x = (float)i0; qv.y = (float)i1; qv.z = p0; qv.w = p1;
        *reinterpret_cast<float4*>(g_topk + (size_t)n * 4) = qv;
        float m = l[0];
#pragma unroll
        for (int e = 1; e < 5; ++e) m = fmaxf(m, l[e]);
        float ssum = 0.f, pe[5];
#pragma unroll
        for (int e = 0; e < 5; ++e) { pe[e] = expf(l[e] - m); ssum += pe[e]; }
        float inv = 1.0f / ssum;
#pragma unroll
        for (int e = 0; e < 5; ++e) H1[tid * 8 + e] = pe[e] * inv;
    }
    __syncthreads();
    for (int st = 32; st > 0; st >>= 1) {
        if (tid < st) {
#pragma unroll
            for (int e = 0; e < 5; ++e)
                H1[tid * 8 + e] += H1[(tid + st) * 8 + e];
        }
        __syncthreads();
    }
    if (tid == 0) {
#pragma unroll
        for (int e = 0; e < 5; ++e)
            g_partial[blockIdx.x * 5 + e] = H1[e];
    }
}

// ---------------------------------------------------------------------------
// Aux loss finalize
// ---------------------------------------------------------------------------
__global__ void aux_kernel(float* __restrict__ out) {
    __shared__ float sums[5];
    int e = threadIdx.x;
    if (e < 5) {
        float acc = 0.f;
        for (int b = 0; b < NBLK; ++b) acc += g_partial[b * 5 + e];
        sums[e] = acc;
    }
    __syncthreads();
    if (threadIdx.x == 0) {
        float ent = 0.f, l2 = 0.f;
#pragma unroll
        for (int k = 0; k < 5; ++k) {
            float avg = sums[k] * (1.0f / (float)N_TOK);
            ent -= avg * logf(avg + 1e-8f);
            float d = avg - 0.2f;
            l2 += d * d;
        }
        l2 *= 0.2f;
        out[OFF_AX] = -ent * 0.01f + 0.01f * l2;
    }
}

// ---------------------------------------------------------------------------
// Top-k combine
// ---------------------------------------------------------------------------
__global__ __launch_bounds__(256)
void combine_traj_kernel(const float* __restrict__ src, float* __restrict__ out) {
    int gx = blockIdx.x * 256 + threadIdx.x;
    int n = gx / T2, c = gx - n * T2;
    float4 qv = *reinterpret_cast<const float4*>(g_topk + (size_t)n * 4);
    int i0 = (int)qv.x, i1 = (int)qv.y;
    float t0 = src[OFF_TA + ((size_t)i0 * N_TOK + n) * T2 + c];
    float t1 = src[OFF_TA + ((size_t)i1 * N_TOK + n) * T2 + c];
    out[OFF_FT + gx] = 0.3f * g_shared_traj[gx] + 0.7f * (qv.z * t0 + qv.w * t1);
}

__global__ __launch_bounds__(256)
void combine_score_kernel(const float* __restrict__ src, float* __restrict__ out) {
    int n = blockIdx.x * 256 + threadIdx.x;
    float4 qv = *reinterpret_cast<const float4*>(g_topk + (size_t)n * 4);
    int i0 = (int)qv.x, i1 = (int)qv.y;
    float s0 = src[OFF_SA + (size_t)i0 * N_TOK + n];
    float s1 = src[OFF_SA + (size_t)i1 * N_TOK + n];
    out[OFF_FS + n] = 0.3f * g_shared_score[n] + 0.7f * (qv.z * s0 + qv.w * s1);
}

// ---------------------------------------------------------------------------
// Launch
// ---------------------------------------------------------------------------
extern "C" void kernel_launch(void* const* d_in, const int* in_sizes, int n_in,
                              void* d_out, int out_size) {
    const float* x    = (const float*)d_in[0];
    const float* rw1  = (const float*)d_in[1];  const float* rb1 = (const float*)d_in[2];
    const float* rw2  = (const float*)d_in[3];  const float* rb2 = (const float*)d_in[4];
    const float* rw3  = (const float*)d_in[5];  const float* rb3 = (const float*)d_in[6];
    const float* stw1 = (const float*)d_in[7];  const float* stb1 = (const float*)d_in[8];
    const float* stw2 = (const float*)d_in[9];  const float* stb2 = (const float*)d_in[10];
    const float* stw3 = (const float*)d_in[11]; const float* stb3 = (const float*)d_in[12];
    const float* ssw1 = (const float*)d_in[13]; const float* ssb1 = (const float*)d_in[14];
    const float* ssw2 = (const float*)d_in[15]; const float* ssb2 = (const float*)d_in[16];
    const float* ssw3 = (const float*)d_in[17]; const float* ssb3 = (const float*)d_in[18];
    const float* etw1 = (const float*)d_in[19]; const float* etb1 = (const float*)d_in[20];
    const float* etw2 = (const float*)d_in[21]; const float* etb2 = (const float*)d_in[22];
    const float* etw3 = (const float*)d_in[23]; const float* etb3 = (const float*)d_in[24];
    const float* esw1 = (const float*)d_in[25]; const float* esb1 = (const float*)d_in[26];
    const float* esw2 = (const float*)d_in[27]; const float* esb2 = (const float*)d_in[28];
    const float* esw3 = (const float*)d_in[29]; const float* esb3 = (const float*)d_in[30];
    float* out = (float*)d_out;

    cudaFuncSetAttribute(traj_mma_kernel, cudaFuncAttributeMaxDynamicSharedMemorySize, SMEM_TC_B);
    cudaFuncSetAttribute(score_kernel,    cudaFuncAttributeMaxDynamicSharedMemorySize, SCORE_SMEM);
    cudaFuncSetAttribute(router_kernel,   cudaFuncAttributeMaxDynamicSharedMemorySize, ROUTER_SMEM);

    // ordered so ncu (-s 5 -c 1) captures traj_mma_kernel (launch #6)
    prep_kernel<<<1572, 256>>>(etw1, etw2, etw3, stw1, stw2, stw3);
    router_kernel<<<NBLK, 256, ROUTER_SMEM>>>(x, rw1, rb1, rw2, rb2, rw3, rb3, out);
    aux_kernel<<<1, 32>>>(out);

    dim3 gS(NBLK, 6);
    score_kernel<<<gS, 256, SCORE_SMEM>>>(x, esw1, esb1, esw2, esb2, esw3, esb3,
                                          ssw1, ssb1, ssw2, ssb2, ssw3, ssb3, out);
    combine_score_kernel<<<N_TOK / 256, 256>>>(out, out);

    dim3 gT(384, 6);
    traj_mma_kernel<<<gT, 256, SMEM_TC_B>>>(x, etb1, etb2, etb3, stb1, stb2, stb3, out);
    combine_traj_kernel<<<(N_TOK * T2) / 256, 256>>>(out, out);
}